// round 1
// baseline (speedup 1.0000x reference)
#include <cuda_runtime.h>
#include <cuda_bf16.h>
#include <cstdint>

#define BATCH 2
#define CH    64
#define NTOK  4608           // D*H*W = 8*24*24
#define BM    64             // queries per block
#define BN    64             // keys per tile
#define SCALE 0.125f         // 1/sqrt(64)

// Scratch: Q/K/V in token-major layout [B][N][C]
__device__ float g_Q[BATCH * NTOK * CH];
__device__ float g_K[BATCH * NTOK * CH];
__device__ float g_V[BATCH * NTOK * CH];

// ---------------------------------------------------------------------------
// Projection: out[b][n][o] = sum_c W[o][c] * inp[b][c][n] + bias[o]
// grid (NTOK/128, B, 3): z=0 -> Q from x, z=1 -> K from h, z=2 -> V from h
// ---------------------------------------------------------------------------
__global__ __launch_bounds__(128) void proj_kernel(
    const float* __restrict__ x, const float* __restrict__ h,
    const float* __restrict__ Wq, const float* __restrict__ bq,
    const float* __restrict__ Wk, const float* __restrict__ bk,
    const float* __restrict__ Wv, const float* __restrict__ bv)
{
    __shared__ float Ws[CH * CH];
    __shared__ float bs[CH];

    const int z = blockIdx.z;
    const float* inp  = (z == 0) ? x  : h;
    const float* W    = (z == 0) ? Wq : (z == 1) ? Wk : Wv;
    const float* bias = (z == 0) ? bq : (z == 1) ? bk : bv;
    float* outbuf     = (z == 0) ? g_Q : (z == 1) ? g_K : g_V;

    const int tid = threadIdx.x;
    #pragma unroll
    for (int i = tid; i < CH * CH; i += 128) Ws[i] = W[i];
    if (tid < CH) bs[tid] = bias[tid];
    __syncthreads();

    const int b = blockIdx.y;
    const int n = blockIdx.x * 128 + tid;   // NTOK % 128 == 0

    // Load the input channel column for this token (coalesced across lanes)
    float xv[CH];
    const float* ic = inp + (size_t)b * CH * NTOK + n;
    #pragma unroll
    for (int c = 0; c < CH; c++) xv[c] = ic[(size_t)c * NTOK];

    float* orow = outbuf + ((size_t)(b * NTOK + n)) * CH;
    #pragma unroll 4
    for (int o = 0; o < CH; o++) {
        float acc = bs[o];
        #pragma unroll
        for (int c = 0; c < CH; c++) acc += Ws[o * CH + c] * xv[c];
        orow[o] = acc;
    }
}

// ---------------------------------------------------------------------------
// Flash attention over N=4608, C=64. grid (NTOK/BM, B), 256 threads.
// Thread mapping: qi = tid & 63 (query within tile), g = tid >> 6 (quarter).
//   score phase : thread computes S[qi][kj], kj = g*16 .. g*16+15
//   softmax     : parallel partial max/exp/sum across the 4 quarters
//   PV phase    : thread owns 16 output channels c = g*16 .. g*16+15 of query qi
// ---------------------------------------------------------------------------
#define SM_FLOATS (64*65 /*Qs*/ + 64*65 /*Ss*/ + 64*64 /*Ks*/ + 64*64 /*Vs*/ \
                   + 64 /*alpha*/ + 64 /*rowl*/ + 256 /*pmax*/ + 256 /*psum*/)
#define SMEM_BYTES (SM_FLOATS * 4)

__global__ __launch_bounds__(256, 1) void attn_kernel(float* __restrict__ out)
{
    extern __shared__ float sm[];
    float* Qs     = sm;                 // [64][65] padded
    float* Ss     = Qs + 64 * 65;       // [64][65] padded
    float* Ks     = Ss + 64 * 65;       // [64][64]
    float* Vs     = Ks + 64 * 64;       // [64][64]
    float* salpha = Vs + 64 * 64;       // [64]
    float* srowl  = salpha + 64;        // [64]
    float* spmax  = srowl + 64;         // [4][64]
    float* spsum  = spmax + 256;        // [4][64]

    const int b   = blockIdx.y;
    const int m0  = blockIdx.x * BM;
    const int tid = threadIdx.x;
    const int qi  = tid & 63;
    const int g   = tid >> 6;

    // Load Q tile into padded smem
    const float* Qg = g_Q + ((size_t)(b * NTOK + m0)) * CH;
    for (int i = tid; i < BM * CH; i += 256) {
        int r = i >> 6, c = i & 63;
        Qs[r * 65 + c] = Qg[r * CH + c];
    }

    float m_run = -1e30f, l_run = 0.f;
    float acc[16];
    #pragma unroll
    for (int i = 0; i < 16; i++) acc[i] = 0.f;
    __syncthreads();

    for (int n0 = 0; n0 < NTOK; n0 += BN) {
        // ---- load K/V tiles (contiguous 16KB each, float4 coalesced) ----
        const float4* Kg = (const float4*)(g_K + ((size_t)(b * NTOK + n0)) * CH);
        const float4* Vg = (const float4*)(g_V + ((size_t)(b * NTOK + n0)) * CH);
        #pragma unroll
        for (int i = tid; i < BN * CH / 4; i += 256) {
            ((float4*)Ks)[i] = Kg[i];
            ((float4*)Vs)[i] = Vg[i];
        }
        __syncthreads();

        // ---- scores: S[qi][kj] for 16 kj, FFMA-bound, K via float4 broadcast ----
        {
            float sacc[16];
            #pragma unroll
            for (int i = 0; i < 16; i++) sacc[i] = 0.f;
            const float* qrow = &Qs[qi * 65];
            #pragma unroll
            for (int c4 = 0; c4 < CH; c4 += 4) {
                const float q0 = qrow[c4], q1 = qrow[c4 + 1];
                const float q2 = qrow[c4 + 2], q3 = qrow[c4 + 3];
                #pragma unroll
                for (int i = 0; i < 16; i++) {
                    const int kj = g * 16 + i;
                    float4 k4 = *(const float4*)&Ks[kj * 64 + c4];
                    sacc[i] += q0 * k4.x;
                    sacc[i] += q1 * k4.y;
                    sacc[i] += q2 * k4.z;
                    sacc[i] += q3 * k4.w;
                }
            }
            float pm = -1e30f;
            #pragma unroll
            for (int i = 0; i < 16; i++) {
                float s = sacc[i] * SCALE;
                Ss[qi * 65 + g * 16 + i] = s;
                pm = fmaxf(pm, s);
            }
            spmax[g * 64 + qi] = pm;
        }
        __syncthreads();

        // ---- row owners combine max, compute rescale alpha ----
        if (tid < 64) {
            float mn = fmaxf(fmaxf(spmax[qi], spmax[64 + qi]),
                             fmaxf(spmax[128 + qi], spmax[192 + qi]));
            mn = fmaxf(m_run, mn);
            salpha[qi] = __expf(m_run - mn);
            spmax[qi]  = mn;     // broadcast m_new (safe: re-written next tile)
            m_run = mn;
        }
        __syncthreads();

        // ---- exp in place + partial sums (all 256 threads) ----
        {
            const float mn = spmax[qi];
            float ps = 0.f;
            #pragma unroll
            for (int i = 0; i < 16; i++) {
                float p = __expf(Ss[qi * 65 + g * 16 + i] - mn);
                Ss[qi * 65 + g * 16 + i] = p;
                ps += p;
            }
            spsum[g * 64 + qi] = ps;
        }
        __syncthreads();

        // ---- row owners update running denominator ----
        if (tid < 64) {
            float s4 = spsum[qi] + spsum[64 + qi] + spsum[128 + qi] + spsum[192 + qi];
            l_run = l_run * salpha[qi] + s4;
        }

        // ---- PV accumulate: acc[c] = acc[c]*alpha + sum_kj P[qi][kj]*V[kj][c] ----
        {
            const float a = salpha[qi];
            #pragma unroll
            for (int i = 0; i < 16; i++) acc[i] *= a;
            const int cbase = g * 16;
            #pragma unroll 4
            for (int kj = 0; kj < BN; kj++) {
                const float p = Ss[qi * 65 + kj];
                #pragma unroll
                for (int c4 = 0; c4 < 16; c4 += 4) {
                    float4 v4 = *(const float4*)&Vs[kj * 64 + cbase + c4];
                    acc[c4]     += p * v4.x;
                    acc[c4 + 1] += p * v4.y;
                    acc[c4 + 2] += p * v4.z;
                    acc[c4 + 3] += p * v4.w;
                }
            }
        }
        __syncthreads();   // protect Ks/Vs/Ss/spmax for next tile
    }

    if (tid < 64) srowl[qi] = l_run;
    __syncthreads();

    // out[b][c][m0+qi], c = g*16+i ; coalesced across qi lanes
    const float inv = 1.f / srowl[qi];
    float* og = out + (size_t)b * CH * NTOK + m0 + qi;
    #pragma unroll
    for (int i = 0; i < 16; i++)
        og[(size_t)(g * 16 + i) * NTOK] = acc[i] * inv;
}

// ---------------------------------------------------------------------------
extern "C" void kernel_launch(void* const* d_in, const int* in_sizes, int n_in,
                              void* d_out, int out_size)
{
    const float* x  = (const float*)d_in[0];
    const float* h  = (const float*)d_in[1];
    const float* Wq = (const float*)d_in[2];
    const float* bq = (const float*)d_in[3];
    const float* Wk = (const float*)d_in[4];
    const float* bk = (const float*)d_in[5];
    const float* Wv = (const float*)d_in[6];
    const float* bv = (const float*)d_in[7];
    float* out = (float*)d_out;

    cudaFuncSetAttribute(attn_kernel,
                         cudaFuncAttributeMaxDynamicSharedMemorySize, SMEM_BYTES);

    proj_kernel<<<dim3(NTOK / 128, BATCH, 3), 128>>>(x, h, Wq, bq, Wk, bk, Wv, bv);
    attn_kernel<<<dim3(NTOK / BM, BATCH), 256, SMEM_BYTES>>>(out);
}

// round 2
// speedup vs baseline: 1.0233x; 1.0233x over previous
#include <cuda_runtime.h>
#include <cuda_bf16.h>
#include <cstdint>

#define BATCH 2
#define CH    64
#define NTOK  4608           // D*H*W = 8*24*24
#define BM    64             // queries per block
#define BN    64             // keys per tile
#define NT    72             // NTOK / BN
#define SCALE 0.125f         // 1/sqrt(64)
#define PADQ  68             // Q row pad (float4-aligned, conflict-free LDS.128)
#define PADS  65             // S row pad (conflict-free scalar)

// Scratch: Q/K/V in token-major layout [B][N][C]
__device__ float g_Q[BATCH * NTOK * CH];
__device__ float g_K[BATCH * NTOK * CH];
__device__ float g_V[BATCH * NTOK * CH];

// ---- packed f32x2 helpers (sm_103a) ---------------------------------------
__device__ __forceinline__ unsigned long long f2_fma(unsigned long long a,
                                                     unsigned long long b,
                                                     unsigned long long c) {
    unsigned long long d;
    asm("fma.rn.f32x2 %0, %1, %2, %3;" : "=l"(d) : "l"(a), "l"(b), "l"(c));
    return d;
}
__device__ __forceinline__ unsigned long long f2_mul(unsigned long long a,
                                                     unsigned long long b) {
    unsigned long long d;
    asm("mul.rn.f32x2 %0, %1, %2;" : "=l"(d) : "l"(a), "l"(b));
    return d;
}
__device__ __forceinline__ unsigned long long f2_pack(float lo, float hi) {
    unsigned long long d;
    asm("mov.b64 %0, {%1, %2};" : "=l"(d) : "f"(lo), "f"(hi));
    return d;
}
__device__ __forceinline__ void f2_unpack(unsigned long long v, float& lo, float& hi) {
    asm("mov.b64 {%0, %1}, %2;" : "=f"(lo), "=f"(hi) : "l"(v));
}

// ---------------------------------------------------------------------------
// Projection: out[b][n][o] = sum_c W[o][c] * inp[b][c][n] + bias[o]
// ---------------------------------------------------------------------------
__global__ __launch_bounds__(128) void proj_kernel(
    const float* __restrict__ x, const float* __restrict__ h,
    const float* __restrict__ Wq, const float* __restrict__ bq,
    const float* __restrict__ Wk, const float* __restrict__ bk,
    const float* __restrict__ Wv, const float* __restrict__ bv)
{
    __shared__ float Ws[CH * CH];
    __shared__ float bs[CH];

    const int z = blockIdx.z;
    const float* inp  = (z == 0) ? x  : h;
    const float* W    = (z == 0) ? Wq : (z == 1) ? Wk : Wv;
    const float* bias = (z == 0) ? bq : (z == 1) ? bk : bv;
    float* outbuf     = (z == 0) ? g_Q : (z == 1) ? g_K : g_V;

    const int tid = threadIdx.x;
    #pragma unroll
    for (int i = tid; i < CH * CH; i += 128) Ws[i] = W[i];
    if (tid < CH) bs[tid] = bias[tid];
    __syncthreads();

    const int b = blockIdx.y;
    const int n = blockIdx.x * 128 + tid;

    float xv[CH];
    const float* ic = inp + (size_t)b * CH * NTOK + n;
    #pragma unroll
    for (int c = 0; c < CH; c++) xv[c] = ic[(size_t)c * NTOK];

    float* orow = outbuf + ((size_t)(b * NTOK + n)) * CH;
    #pragma unroll 4
    for (int o = 0; o < CH; o++) {
        float acc = bs[o];
        #pragma unroll
        for (int c = 0; c < CH; c++) acc += Ws[o * CH + c] * xv[c];
        orow[o] = acc;
    }
}

// ---------------------------------------------------------------------------
// Flash attention, 512 threads. qi = tid&63, g = tid>>6 (0..7).
//   scores : thread computes S[qi][g*8 .. g*8+7] with packed FFMA2
//   PV     : thread owns output channels g*8 .. g*8+7 of row qi
// K/V double-buffered in smem; next tile prefetched to regs during compute.
// ---------------------------------------------------------------------------
#define SM_FLOATS (64*PADQ + 64*PADS + 2*64*64 + 2*64*64 + 64 + 64 + 512 + 512)
#define SMEM_BYTES (SM_FLOATS * 4)

__global__ __launch_bounds__(512, 1) void attn_kernel(float* __restrict__ out)
{
    extern __shared__ float sm[];
    float* Qs     = sm;                      // [64][PADQ]
    float* Ss     = Qs + 64 * PADQ;          // [64][PADS]
    float* Ks     = Ss + 64 * PADS;          // [2][64][64]
    float* Vs     = Ks + 2 * 64 * 64;        // [2][64][64]
    float* salpha = Vs + 2 * 64 * 64;        // [64]
    float* srowl  = salpha + 64;             // [64]
    float* spmax  = srowl + 64;              // [8][64]
    float* spsum  = spmax + 512;             // [8][64]

    const int b   = blockIdx.y;
    const int m0  = blockIdx.x * BM;
    const int tid = threadIdx.x;
    const int qi  = tid & 63;
    const int g   = tid >> 6;
    const int cbase = g * 8;

    // Load Q tile into padded smem (float4)
    const float4* Qg = (const float4*)(g_Q + ((size_t)(b * NTOK + m0)) * CH);
    #pragma unroll
    for (int i = tid; i < BM * CH / 4; i += 512) {
        int r = i >> 4, c4 = (i & 15) * 4;
        *(float4*)&Qs[r * PADQ + c4] = Qg[i];
    }

    // Preload tile 0 into buffer 0
    {
        const float4* Kg = (const float4*)(g_K + ((size_t)(b * NTOK)) * CH);
        const float4* Vg = (const float4*)(g_V + ((size_t)(b * NTOK)) * CH);
        ((float4*)Ks)[tid]       = Kg[tid];
        ((float4*)Ks)[tid + 512] = Kg[tid + 512];
        ((float4*)Vs)[tid]       = Vg[tid];
        ((float4*)Vs)[tid + 512] = Vg[tid + 512];
    }

    float m_run = -1e30f, l_run = 0.f;
    unsigned long long acc2[4] = {0ull, 0ull, 0ull, 0ull};
    __syncthreads();

    for (int t = 0; t < NT; t++) {
        const int cb = t & 1, nb = cb ^ 1;
        const int nsrc = (t + 1 < NT) ? (t + 1) * BN : 0;

        // ---- prefetch next K/V tile into registers (latency hidden) ----
        const float4* Kg = (const float4*)(g_K + ((size_t)(b * NTOK + nsrc)) * CH);
        const float4* Vg = (const float4*)(g_V + ((size_t)(b * NTOK + nsrc)) * CH);
        float4 kr0 = Kg[tid], kr1 = Kg[tid + 512];
        float4 vr0 = Vg[tid], vr1 = Vg[tid + 512];

        // ---- scores: 8 kj per thread, packed FFMA2 ----
        const float* Kcur = Ks + cb * 64 * 64;
        unsigned long long sacc2[8];
        #pragma unroll
        for (int i = 0; i < 8; i++) sacc2[i] = 0ull;

        #pragma unroll
        for (int c4 = 0; c4 < CH; c4 += 4) {
            const ulonglong2 q2 = *(const ulonglong2*)&Qs[qi * PADQ + c4];
            #pragma unroll
            for (int i = 0; i < 8; i++) {
                const ulonglong2 kk =
                    *(const ulonglong2*)&Kcur[(cbase + i) * 64 + c4];
                sacc2[i] = f2_fma(q2.x, kk.x, sacc2[i]);
                sacc2[i] = f2_fma(q2.y, kk.y, sacc2[i]);
            }
        }
        float pm = -1e30f;
        #pragma unroll
        for (int i = 0; i < 8; i++) {
            float lo, hi;
            f2_unpack(sacc2[i], lo, hi);
            float s = (lo + hi) * SCALE;
            Ss[qi * PADS + cbase + i] = s;
            pm = fmaxf(pm, s);
        }
        spmax[g * 64 + qi] = pm;
        __syncthreads();                               // A

        // ---- row owners: combine max, rescale factor ----
        if (tid < 64) {
            float mn = m_run;
            #pragma unroll
            for (int gg = 0; gg < 8; gg++) mn = fmaxf(mn, spmax[gg * 64 + qi]);
            salpha[qi] = __expf(m_run - mn);
            spmax[qi]  = mn;
            m_run = mn;
        }
        __syncthreads();                               // B

        // ---- exp in place + partial sums ----
        {
            const float mn = spmax[qi];
            float ps = 0.f;
            #pragma unroll
            for (int i = 0; i < 8; i++) {
                float p = __expf(Ss[qi * PADS + cbase + i] - mn);
                Ss[qi * PADS + cbase + i] = p;
                ps += p;
            }
            spsum[g * 64 + qi] = ps;
        }
        __syncthreads();                               // C

        if (tid < 64) {
            float s = 0.f;
            #pragma unroll
            for (int gg = 0; gg < 8; gg++) s += spsum[gg * 64 + qi];
            l_run = l_run * salpha[qi] + s;
        }

        // ---- PV: 8 channels per thread, packed FFMA2 ----
        {
            const float a = salpha[qi];
            const unsigned long long aa = f2_pack(a, a);
            #pragma unroll
            for (int j = 0; j < 4; j++) acc2[j] = f2_mul(acc2[j], aa);

            const float* Vcur = Vs + cb * 64 * 64;
            #pragma unroll 8
            for (int kj = 0; kj < BN; kj++) {
                const float p = Ss[qi * PADS + kj];
                const unsigned long long pp = f2_pack(p, p);
                const ulonglong2* vr = (const ulonglong2*)&Vcur[kj * 64 + cbase];
                const ulonglong2 v0 = vr[0], v1 = vr[1];
                acc2[0] = f2_fma(pp, v0.x, acc2[0]);
                acc2[1] = f2_fma(pp, v0.y, acc2[1]);
                acc2[2] = f2_fma(pp, v1.x, acc2[2]);
                acc2[3] = f2_fma(pp, v1.y, acc2[3]);
            }
        }

        // ---- store prefetched tile into the other buffer ----
        {
            float4* Kn = (float4*)(Ks + nb * 64 * 64);
            float4* Vn = (float4*)(Vs + nb * 64 * 64);
            Kn[tid] = kr0; Kn[tid + 512] = kr1;
            Vn[tid] = vr0; Vn[tid + 512] = vr1;
        }
        __syncthreads();                               // D
    }

    if (tid < 64) srowl[qi] = l_run;
    __syncthreads();

    const float inv = 1.f / srowl[qi];
    float* og = out + (size_t)b * CH * NTOK + m0 + qi;
    #pragma unroll
    for (int j = 0; j < 4; j++) {
        float lo, hi;
        f2_unpack(acc2[j], lo, hi);
        og[(size_t)(cbase + 2 * j) * NTOK]     = lo * inv;
        og[(size_t)(cbase + 2 * j + 1) * NTOK] = hi * inv;
    }
}

// ---------------------------------------------------------------------------
extern "C" void kernel_launch(void* const* d_in, const int* in_sizes, int n_in,
                              void* d_out, int out_size)
{
    const float* x  = (const float*)d_in[0];
    const float* h  = (const float*)d_in[1];
    const float* Wq = (const float*)d_in[2];
    const float* bq = (const float*)d_in[3];
    const float* Wk = (const float*)d_in[4];
    const float* bk = (const float*)d_in[5];
    const float* Wv = (const float*)d_in[6];
    const float* bv = (const float*)d_in[7];
    float* out = (float*)d_out;

    cudaFuncSetAttribute(attn_kernel,
                         cudaFuncAttributeMaxDynamicSharedMemorySize, SMEM_BYTES);

    proj_kernel<<<dim3(NTOK / 128, BATCH, 3), 128>>>(x, h, Wq, bq, Wk, bk, Wv, bv);
    attn_kernel<<<dim3(NTOK / BM, BATCH), 512, SMEM_BYTES>>>(out);
}

// round 3
// speedup vs baseline: 3.2331x; 3.1594x over previous
#include <cuda_runtime.h>
#include <cuda_bf16.h>
#include <cstdint>

#define BATCH 2
#define CH    64
#define NTOK  4608
#define BM    64
#define BN    64
#define NT    72               // NTOK / BN
#define SCALE 0.125f
#define LOG2E 1.4426950408889634f
#define PK    68               // K row pad (floats)
#define PVD   72               // V row pad
#define PS    68               // P/Q row pad

// Scratch: Q/K/V token-major [B][N][C]; pre-rounded to tf32 (Q pre-scaled)
__device__ float g_Q[BATCH * NTOK * CH];
__device__ float g_K[BATCH * NTOK * CH];
__device__ float g_V[BATCH * NTOK * CH];

// ---------------------------------------------------------------------------
__device__ __forceinline__ float to_tf32(float x) {
    uint32_t u;
    asm("cvt.rna.tf32.f32 %0, %1;" : "=r"(u) : "f"(x));
    return __uint_as_float(u);
}
__device__ __forceinline__ uint32_t to_tf32_bits(float x) {
    uint32_t u;
    asm("cvt.rna.tf32.f32 %0, %1;" : "=r"(u) : "f"(x));
    return u;
}

__device__ __forceinline__ void mma_tf32(float* c, const uint32_t* a,
                                         uint32_t b0, uint32_t b1) {
    asm volatile(
        "mma.sync.aligned.m16n8k8.row.col.f32.tf32.tf32.f32 "
        "{%0,%1,%2,%3}, {%4,%5,%6,%7}, {%8,%9}, {%0,%1,%2,%3};"
        : "+f"(c[0]), "+f"(c[1]), "+f"(c[2]), "+f"(c[3])
        : "r"(a[0]), "r"(a[1]), "r"(a[2]), "r"(a[3]), "r"(b0), "r"(b1));
}

__device__ __forceinline__ void cp16(uint32_t dst, const float* src) {
    asm volatile("cp.async.ca.shared.global [%0], [%1], 16;"
                 :: "r"(dst), "l"(src));
}

// ---------------------------------------------------------------------------
// Projection (unchanged math) + tf32 pre-round; Q pre-scaled by SCALE*LOG2E
// ---------------------------------------------------------------------------
__global__ __launch_bounds__(128) void proj_kernel(
    const float* __restrict__ x, const float* __restrict__ h,
    const float* __restrict__ Wq, const float* __restrict__ bq,
    const float* __restrict__ Wk, const float* __restrict__ bk,
    const float* __restrict__ Wv, const float* __restrict__ bv)
{
    __shared__ float Ws[CH * CH];
    __shared__ float bs[CH];

    const int z = blockIdx.z;
    const float* inp  = (z == 0) ? x  : h;
    const float* W    = (z == 0) ? Wq : (z == 1) ? Wk : Wv;
    const float* bias = (z == 0) ? bq : (z == 1) ? bk : bv;
    float* outbuf     = (z == 0) ? g_Q : (z == 1) ? g_K : g_V;

    const int tid = threadIdx.x;
    #pragma unroll
    for (int i = tid; i < CH * CH; i += 128) Ws[i] = W[i];
    if (tid < CH) bs[tid] = bias[tid];
    __syncthreads();

    const int b = blockIdx.y;
    const int n = blockIdx.x * 128 + tid;

    float xv[CH];
    const float* ic = inp + (size_t)b * CH * NTOK + n;
    #pragma unroll
    for (int c = 0; c < CH; c++) xv[c] = ic[(size_t)c * NTOK];

    const float qscale = SCALE * LOG2E;
    float* orow = outbuf + ((size_t)(b * NTOK + n)) * CH;
    #pragma unroll 4
    for (int o = 0; o < CH; o++) {
        float acc = bs[o];
        #pragma unroll
        for (int c = 0; c < CH; c++) acc += Ws[o * CH + c] * xv[c];
        if (z == 0) acc *= qscale;
        orow[o] = to_tf32(acc);
    }
}

// ---------------------------------------------------------------------------
// Tensor-core flash attention. 256 threads = 8 warps.
// warp w: wm = w&3 (query rows 16*wm..16*wm+15), wn = w>>2 (kj/c half).
// ---------------------------------------------------------------------------
#define SM_FLOATS (2*64*PK + 2*64*PVD + 64*PS + 64*4 + 128*2)
#define SMEM_BYTES (SM_FLOATS * 4)

__global__ __launch_bounds__(256, 1) void attn_kernel(float* __restrict__ out)
{
    extern __shared__ float sm[];
    float* Ks     = sm;                        // [2][64][PK]
    float* Vs     = Ks + 2 * 64 * PK;          // [2][64][PVD]
    float* Ss     = Vs + 2 * 64 * PVD;         // [64][PS]  (Q stage, then P)
    float* srowm  = Ss + 64 * PS;              // [64]
    float* srowl  = srowm + 64;                // [64]
    float* salpha = srowl + 64;                // [64]
    float* smnew  = salpha + 64;               // [64]
    float* spmax  = smnew + 64;                // [2][64]
    float* spsum  = spmax + 128;               // [2][64]

    const int b    = blockIdx.y;
    const int m0   = blockIdx.x * BM;
    const int tid  = threadIdx.x;
    const int lane = tid & 31;
    const int w    = tid >> 5;
    const int wm   = w & 3;
    const int wn   = w >> 2;
    const int gid  = lane >> 2;        // group id 0..7
    const int lc   = lane & 3;         // thread-in-group 0..3
    const int rlow  = wm * 16 + gid;   // block-local query row (low)
    const int rhigh = rlow + 8;

    const uint32_t smem_base = (uint32_t)__cvta_generic_to_shared(sm);

    // ---- stage Q via smem, build persistent A-fragments ----
    const float4* Qg = (const float4*)(g_Q + (size_t)(b * NTOK + m0) * CH);
    #pragma unroll
    for (int i = tid; i < BM * CH / 4; i += 256) {
        int r = i >> 4, c4 = (i & 15) * 4;
        *(float4*)&Ss[r * PS + c4] = Qg[i];
    }
    if (tid < 64) { srowm[tid] = -1e30f; srowl[tid] = 0.f; }
    __syncthreads();

    uint32_t qa[8][4];
    #pragma unroll
    for (int kt = 0; kt < 8; kt++) {
        qa[kt][0] = __float_as_uint(Ss[rlow  * PS + kt * 8 + lc]);
        qa[kt][1] = __float_as_uint(Ss[rhigh * PS + kt * 8 + lc]);
        qa[kt][2] = __float_as_uint(Ss[rlow  * PS + kt * 8 + lc + 4]);
        qa[kt][3] = __float_as_uint(Ss[rhigh * PS + kt * 8 + lc + 4]);
    }
    __syncthreads();   // Ss now free for P

    // ---- prologue: async-load tile 0 into buffer 0 ----
    {
        const float* Kg = g_K + (size_t)(b * NTOK) * CH;
        const float* Vg = g_V + (size_t)(b * NTOK) * CH;
        #pragma unroll
        for (int i = 0; i < 4; i++) {
            int j = tid + i * 256;               // 0..1023
            int r = j >> 4, c = (j & 15) * 4;
            cp16(smem_base + (uint32_t)((r * PK + c) * 4), Kg + r * 64 + c);
            cp16(smem_base + (uint32_t)((2 * 64 * PK + r * PVD + c) * 4),
                 Vg + r * 64 + c);
        }
        asm volatile("cp.async.commit_group;");
    }

    float acc[4][4];
    #pragma unroll
    for (int nt = 0; nt < 4; nt++)
        #pragma unroll
        for (int i = 0; i < 4; i++) acc[nt][i] = 0.f;

    for (int t = 0; t < NT; t++) {
        const int cb = t & 1;
        asm volatile("cp.async.wait_group 0;");
        __syncthreads();                                   // bar A: tile ready

        // prefetch next tile into other buffer
        {
            const int tn = (t + 1 < NT) ? t + 1 : 0;
            const int nb = cb ^ 1;
            const float* Kg = g_K + (size_t)(b * NTOK + tn * BN) * CH;
            const float* Vg = g_V + (size_t)(b * NTOK + tn * BN) * CH;
            #pragma unroll
            for (int i = 0; i < 4; i++) {
                int j = tid + i * 256;
                int r = j >> 4, c = (j & 15) * 4;
                cp16(smem_base + (uint32_t)((nb * 64 * PK + r * PK + c) * 4),
                     Kg + r * 64 + c);
                cp16(smem_base + (uint32_t)((2 * 64 * PK + nb * 64 * PVD +
                                             r * PVD + c) * 4),
                     Vg + r * 64 + c);
            }
            asm volatile("cp.async.commit_group;");
        }

        // ---- scores: S[16m][32kj] per warp via 32 HMMA ----
        const float* Kc = Ks + cb * 64 * PK;
        float s[4][4];
        #pragma unroll
        for (int nt = 0; nt < 4; nt++)
            #pragma unroll
            for (int i = 0; i < 4; i++) s[nt][i] = 0.f;

        #pragma unroll
        for (int kt = 0; kt < 8; kt++) {
            #pragma unroll
            for (int nt = 0; nt < 4; nt++) {
                const int kj = wn * 32 + nt * 8 + gid;
                uint32_t b0 = __float_as_uint(Kc[kj * PK + kt * 8 + lc]);
                uint32_t b1 = __float_as_uint(Kc[kj * PK + kt * 8 + lc + 4]);
                mma_tf32(s[nt], qa[kt], b0, b1);
            }
        }

        // ---- per-row max (thread-local + 4-lane shuffle) ----
        float mlo = -1e30f, mhi = -1e30f;
        #pragma unroll
        for (int nt = 0; nt < 4; nt++) {
            mlo = fmaxf(mlo, fmaxf(s[nt][0], s[nt][1]));
            mhi = fmaxf(mhi, fmaxf(s[nt][2], s[nt][3]));
        }
        mlo = fmaxf(mlo, __shfl_xor_sync(0xffffffffu, mlo, 1));
        mlo = fmaxf(mlo, __shfl_xor_sync(0xffffffffu, mlo, 2));
        mhi = fmaxf(mhi, __shfl_xor_sync(0xffffffffu, mhi, 1));
        mhi = fmaxf(mhi, __shfl_xor_sync(0xffffffffu, mhi, 2));
        if (lc == 0) {
            spmax[wn * 64 + rlow]  = mlo;
            spmax[wn * 64 + rhigh] = mhi;
        }
        __syncthreads();                                   // bar B

        if (tid < 64) {
            float mo = srowm[tid];
            float mn = fmaxf(mo, fmaxf(spmax[tid], spmax[64 + tid]));
            salpha[tid] = exp2f(mo - mn);
            smnew[tid]  = mn;
            srowm[tid]  = mn;
        }
        __syncthreads();                                   // bar C

        // ---- exp (base-2, Q pre-scaled) + partial sums + store P(tf32) ----
        const float mnlo = smnew[rlow], mnhi = smnew[rhigh];
        const float alo  = salpha[rlow], ahi = salpha[rhigh];
        float plo = 0.f, phi = 0.f;
        #pragma unroll
        for (int nt = 0; nt < 4; nt++) {
            float p0 = exp2f(s[nt][0] - mnlo);
            float p1 = exp2f(s[nt][1] - mnlo);
            float p2 = exp2f(s[nt][2] - mnhi);
            float p3 = exp2f(s[nt][3] - mnhi);
            plo += p0 + p1;
            phi += p2 + p3;
            float2 lo2 = make_float2(__uint_as_float(to_tf32_bits(p0)),
                                     __uint_as_float(to_tf32_bits(p1)));
            float2 hi2 = make_float2(__uint_as_float(to_tf32_bits(p2)),
                                     __uint_as_float(to_tf32_bits(p3)));
            *(float2*)&Ss[rlow  * PS + wn * 32 + nt * 8 + 2 * lc] = lo2;
            *(float2*)&Ss[rhigh * PS + wn * 32 + nt * 8 + 2 * lc] = hi2;
        }
        plo += __shfl_xor_sync(0xffffffffu, plo, 1);
        plo += __shfl_xor_sync(0xffffffffu, plo, 2);
        phi += __shfl_xor_sync(0xffffffffu, phi, 1);
        phi += __shfl_xor_sync(0xffffffffu, phi, 2);
        if (lc == 0) {
            spsum[wn * 64 + rlow]  = plo;
            spsum[wn * 64 + rhigh] = phi;
        }
        __syncthreads();                                   // bar D

        if (tid < 64)
            srowl[tid] = srowl[tid] * salpha[tid] + spsum[tid] + spsum[64 + tid];

        // ---- PV: out[16m][32c] += P[16m][64kj] * V[64kj][32c] ----
        #pragma unroll
        for (int nt = 0; nt < 4; nt++) {
            acc[nt][0] *= alo; acc[nt][1] *= alo;
            acc[nt][2] *= ahi; acc[nt][3] *= ahi;
        }
        const float* Vc = Vs + cb * 64 * PVD;
        #pragma unroll
        for (int kt = 0; kt < 8; kt++) {
            uint32_t pa[4];
            pa[0] = __float_as_uint(Ss[rlow  * PS + kt * 8 + lc]);
            pa[1] = __float_as_uint(Ss[rhigh * PS + kt * 8 + lc]);
            pa[2] = __float_as_uint(Ss[rlow  * PS + kt * 8 + lc + 4]);
            pa[3] = __float_as_uint(Ss[rhigh * PS + kt * 8 + lc + 4]);
            #pragma unroll
            for (int nt = 0; nt < 4; nt++) {
                const int c = wn * 32 + nt * 8 + gid;
                uint32_t b0 = __float_as_uint(Vc[(kt * 8 + lc) * PVD + c]);
                uint32_t b1 = __float_as_uint(Vc[(kt * 8 + lc + 4) * PVD + c]);
                mma_tf32(acc[nt], pa, b0, b1);
            }
        }
    }

    __syncthreads();   // srowl final
    const float ilo = 1.f / srowl[rlow];
    const float ihi = 1.f / srowl[rhigh];

    float* ob = out + (size_t)b * CH * NTOK + m0;
    #pragma unroll
    for (int nt = 0; nt < 4; nt++) {
        const int c = wn * 32 + nt * 8 + 2 * lc;
        ob[(size_t)c * NTOK + rlow]        = acc[nt][0] * ilo;
        ob[(size_t)(c + 1) * NTOK + rlow]  = acc[nt][1] * ilo;
        ob[(size_t)c * NTOK + rhigh]       = acc[nt][2] * ihi;
        ob[(size_t)(c + 1) * NTOK + rhigh] = acc[nt][3] * ihi;
    }
}

// ---------------------------------------------------------------------------
extern "C" void kernel_launch(void* const* d_in, const int* in_sizes, int n_in,
                              void* d_out, int out_size)
{
    const float* x  = (const float*)d_in[0];
    const float* h  = (const float*)d_in[1];
    const float* Wq = (const float*)d_in[2];
    const float* bq = (const float*)d_in[3];
    const float* Wk = (const float*)d_in[4];
    const float* bk = (const float*)d_in[5];
    const float* Wv = (const float*)d_in[6];
    const float* bv = (const float*)d_in[7];
    float* out = (float*)d_out;

    cudaFuncSetAttribute(attn_kernel,
                         cudaFuncAttributeMaxDynamicSharedMemorySize, SMEM_BYTES);

    proj_kernel<<<dim3(NTOK / 128, BATCH, 3), 128>>>(x, h, Wq, bq, Wk, bk, Wv, bv);
    attn_kernel<<<dim3(NTOK / BM, BATCH), 256, SMEM_BYTES>>>(out);
}

// round 4
// speedup vs baseline: 4.4039x; 1.3621x over previous
#include <cuda_runtime.h>
#include <cuda_fp16.h>
#include <cstdint>

#define BATCH 2
#define CH    64
#define NTOK  4608
#define BM    64
#define BN    64
#define NT    72               // NTOK / BN
#define SCALE 0.125f
#define LOG2E 1.4426950408889634f
#define PH    72               // padded row length in halves (144 B = 36 words)

// Scratch (fp16): Q,K token-major [B][N][C]; V channel-major [B][C][N]
__device__ __half g_Q[BATCH * NTOK * CH];
__device__ __half g_K[BATCH * NTOK * CH];
__device__ __half g_V[BATCH * CH * NTOK];

// ---------------------------------------------------------------------------
__device__ __forceinline__ void mma_f16(float* c, const uint32_t* a,
                                        uint32_t b0, uint32_t b1) {
    asm volatile(
        "mma.sync.aligned.m16n8k16.row.col.f32.f16.f16.f32 "
        "{%0,%1,%2,%3}, {%4,%5,%6,%7}, {%8,%9}, {%0,%1,%2,%3};"
        : "+f"(c[0]), "+f"(c[1]), "+f"(c[2]), "+f"(c[3])
        : "r"(a[0]), "r"(a[1]), "r"(a[2]), "r"(a[3]), "r"(b0), "r"(b1));
}
__device__ __forceinline__ void cp16(uint32_t dst, const void* src) {
    asm volatile("cp.async.ca.shared.global [%0], [%1], 16;"
                 :: "r"(dst), "l"(src));
}

// ---------------------------------------------------------------------------
// Projection -> fp16. z=0: Q from x (pre-scaled by SCALE*LOG2E), z=1: K from h,
// z=2: V from h stored TRANSPOSED [b][c][n].
// ---------------------------------------------------------------------------
__global__ __launch_bounds__(128) void proj_kernel(
    const float* __restrict__ x, const float* __restrict__ h,
    const float* __restrict__ Wq, const float* __restrict__ bq,
    const float* __restrict__ Wk, const float* __restrict__ bk,
    const float* __restrict__ Wv, const float* __restrict__ bv)
{
    __shared__ float Ws[CH * CH];
    __shared__ float bs[CH];

    const int z = blockIdx.z;
    const float* inp  = (z == 0) ? x  : h;
    const float* W    = (z == 0) ? Wq : (z == 1) ? Wk : Wv;
    const float* bias = (z == 0) ? bq : (z == 1) ? bk : bv;

    const int tid = threadIdx.x;
    #pragma unroll
    for (int i = tid; i < CH * CH; i += 128) Ws[i] = W[i];
    if (tid < CH) bs[tid] = bias[tid];
    __syncthreads();

    const int b = blockIdx.y;
    const int n = blockIdx.x * 128 + tid;

    float xv[CH];
    const float* ic = inp + (size_t)b * CH * NTOK + n;
    #pragma unroll
    for (int c = 0; c < CH; c++) xv[c] = ic[(size_t)c * NTOK];

    const float qs = SCALE * LOG2E;
    #pragma unroll 4
    for (int o = 0; o < CH; o++) {
        float acc = bs[o];
        #pragma unroll
        for (int c = 0; c < CH; c++) acc += Ws[o * CH + c] * xv[c];
        if (z == 0)
            g_Q[((size_t)(b * NTOK + n)) * CH + o] = __float2half_rn(acc * qs);
        else if (z == 1)
            g_K[((size_t)(b * NTOK + n)) * CH + o] = __float2half_rn(acc);
        else
            g_V[(size_t)b * CH * NTOK + (size_t)o * NTOK + n] = __float2half_rn(acc);
    }
}

// ---------------------------------------------------------------------------
// fp16 tensor-core flash attention. 512 threads = 16 warps (4 wm x 4 wn),
// warp tile m16 x n16 (2 x m16n8k16 per k-chunk).
// smem byte map:
//   Ks : [2][64][PH]h  @0      (2 x 9216 B)
//   Vt : [2][64][PH]h  @18432  (V transposed: row=channel, col=key)
//   Ss : [64][PH]h     @36864  (Q staging, then P)
//   stats (f32)        @46080
// ---------------------------------------------------------------------------
#define KS_B   0
#define VT_B   18432
#define SS_B   36864
#define ST_B   46080
#define SMEM_BYTES (ST_B + (64*4)*4 + 256*4*2)   // 49152

__global__ __launch_bounds__(512, 1) void attn_kernel(float* __restrict__ out)
{
    extern __shared__ char smc[];
    __half* Ks    = (__half*)(smc + KS_B);
    __half* Vt    = (__half*)(smc + VT_B);
    __half* Ss    = (__half*)(smc + SS_B);
    float* srowm  = (float*)(smc + ST_B);
    float* srowl  = srowm + 64;
    float* salpha = srowl + 64;
    float* smnew  = salpha + 64;
    float* spmax  = smnew + 64;      // [4][64]
    float* spsum  = spmax + 256;     // [4][64]

    const int b    = blockIdx.y;
    const int m0   = blockIdx.x * BM;
    const int tid  = threadIdx.x;
    const int lane = tid & 31;
    const int w    = tid >> 5;
    const int wm   = w >> 2;
    const int wn   = w & 3;
    const int gid  = lane >> 2;
    const int lc   = lane & 3;
    const int rlow  = wm * 16 + gid;
    const int rhigh = rlow + 8;

    const uint32_t sb = (uint32_t)__cvta_generic_to_shared(smc);
    const int rr = tid >> 3;          // 0..63 (row)
    const int cc = tid & 7;           // 0..7  (16B chunk)

    // ---- prologue: async load K/V tile0 + Q tile ----
    {
        const __half* Kg = g_K + ((size_t)(b * NTOK) + rr) * CH + cc * 8;
        const __half* Vg = g_V + (size_t)b * CH * NTOK + (size_t)rr * NTOK + cc * 8;
        const __half* Qg = g_Q + ((size_t)(b * NTOK + m0) + rr) * CH + cc * 8;
        cp16(sb + KS_B + rr * 144 + cc * 16, Kg);
        cp16(sb + VT_B + rr * 144 + cc * 16, Vg);
        cp16(sb + SS_B + rr * 144 + cc * 16, Qg);
        asm volatile("cp.async.commit_group;");
    }
    if (tid < 64) { srowm[tid] = -1e30f; srowl[tid] = 0.f; }
    asm volatile("cp.async.wait_group 0;" ::: "memory");
    __syncthreads();

    // ---- persistent Q A-fragments ----
    uint32_t qa[4][4];
    #pragma unroll
    for (int kt = 0; kt < 4; kt++) {
        qa[kt][0] = *(const uint32_t*)&Ss[rlow  * PH + kt * 16 + 2 * lc];
        qa[kt][1] = *(const uint32_t*)&Ss[rhigh * PH + kt * 16 + 2 * lc];
        qa[kt][2] = *(const uint32_t*)&Ss[rlow  * PH + kt * 16 + 2 * lc + 8];
        qa[kt][3] = *(const uint32_t*)&Ss[rhigh * PH + kt * 16 + 2 * lc + 8];
    }

    float acc[2][4];
    #pragma unroll
    for (int nt = 0; nt < 2; nt++)
        #pragma unroll
        for (int i = 0; i < 4; i++) acc[nt][i] = 0.f;

    for (int t = 0; t < NT; t++) {
        const int cb = t & 1;
        asm volatile("cp.async.wait_group 0;" ::: "memory");
        __syncthreads();                                   // bar A

        // prefetch next tile
        {
            const int tn = (t + 1 < NT) ? t + 1 : 0;
            const int nb = cb ^ 1;
            const __half* Kg = g_K + ((size_t)(b * NTOK + tn * BN) + rr) * CH + cc * 8;
            const __half* Vg = g_V + (size_t)b * CH * NTOK + (size_t)rr * NTOK
                               + tn * BN + cc * 8;
            cp16(sb + KS_B + nb * 9216 + rr * 144 + cc * 16, Kg);
            cp16(sb + VT_B + nb * 9216 + rr * 144 + cc * 16, Vg);
            asm volatile("cp.async.commit_group;");
        }

        // ---- scores: warp computes S[16m][16n] ----
        const __half* Kc = Ks + cb * (64 * PH);
        float s[2][4];
        #pragma unroll
        for (int nt = 0; nt < 2; nt++)
            #pragma unroll
            for (int i = 0; i < 4; i++) s[nt][i] = 0.f;

        #pragma unroll
        for (int kt = 0; kt < 4; kt++) {
            #pragma unroll
            for (int nt = 0; nt < 2; nt++) {
                const int kj = wn * 16 + nt * 8 + gid;
                uint32_t b0 = *(const uint32_t*)&Kc[kj * PH + kt * 16 + 2 * lc];
                uint32_t b1 = *(const uint32_t*)&Kc[kj * PH + kt * 16 + 2 * lc + 8];
                mma_f16(s[nt], qa[kt], b0, b1);
            }
        }

        // ---- per-row max partials ----
        float mlo = fmaxf(fmaxf(s[0][0], s[0][1]), fmaxf(s[1][0], s[1][1]));
        float mhi = fmaxf(fmaxf(s[0][2], s[0][3]), fmaxf(s[1][2], s[1][3]));
        mlo = fmaxf(mlo, __shfl_xor_sync(0xffffffffu, mlo, 1));
        mlo = fmaxf(mlo, __shfl_xor_sync(0xffffffffu, mlo, 2));
        mhi = fmaxf(mhi, __shfl_xor_sync(0xffffffffu, mhi, 1));
        mhi = fmaxf(mhi, __shfl_xor_sync(0xffffffffu, mhi, 2));
        if (lc == 0) {
            spmax[wn * 64 + rlow]  = mlo;
            spmax[wn * 64 + rhigh] = mhi;
        }
        __syncthreads();                                   // bar B

        if (tid < 64) {
            float mo = srowm[tid];
            float mn = fmaxf(fmaxf(spmax[tid], spmax[64 + tid]),
                             fmaxf(spmax[128 + tid], spmax[192 + tid]));
            mn = fmaxf(mo, mn);
            salpha[tid] = exp2f(mo - mn);
            smnew[tid]  = mn;
            srowm[tid]  = mn;
        }
        __syncthreads();                                   // bar C

        // ---- exp (base-2; Q pre-scaled) + partial sums + P store (fp16) ----
        const float mnlo = smnew[rlow], mnhi = smnew[rhigh];
        const float alo  = salpha[rlow], ahi = salpha[rhigh];
        float plo = 0.f, phi = 0.f;
        #pragma unroll
        for (int nt = 0; nt < 2; nt++) {
            float p0 = exp2f(s[nt][0] - mnlo);
            float p1 = exp2f(s[nt][1] - mnlo);
            float p2 = exp2f(s[nt][2] - mnhi);
            float p3 = exp2f(s[nt][3] - mnhi);
            plo += p0 + p1;
            phi += p2 + p3;
            const int col = wn * 16 + nt * 8 + 2 * lc;
            *(__half2*)&Ss[rlow  * PH + col] = __floats2half2_rn(p0, p1);
            *(__half2*)&Ss[rhigh * PH + col] = __floats2half2_rn(p2, p3);
        }
        plo += __shfl_xor_sync(0xffffffffu, plo, 1);
        plo += __shfl_xor_sync(0xffffffffu, plo, 2);
        phi += __shfl_xor_sync(0xffffffffu, phi, 1);
        phi += __shfl_xor_sync(0xffffffffu, phi, 2);
        if (lc == 0) {
            spsum[wn * 64 + rlow]  = plo;
            spsum[wn * 64 + rhigh] = phi;
        }
        __syncthreads();                                   // bar D

        if (tid < 64)
            srowl[tid] = srowl[tid] * salpha[tid]
                       + spsum[tid] + spsum[64 + tid]
                       + spsum[128 + tid] + spsum[192 + tid];

        // ---- PV: warp computes O[16m][16c] += P[16m][64k] * V[64k][16c] ----
        #pragma unroll
        for (int nt = 0; nt < 2; nt++) {
            acc[nt][0] *= alo; acc[nt][1] *= alo;
            acc[nt][2] *= ahi; acc[nt][3] *= ahi;
        }
        const __half* Vc = Vt + cb * (64 * PH);
        #pragma unroll
        for (int kt = 0; kt < 4; kt++) {
            uint32_t pa[4];
            pa[0] = *(const uint32_t*)&Ss[rlow  * PH + kt * 16 + 2 * lc];
            pa[1] = *(const uint32_t*)&Ss[rhigh * PH + kt * 16 + 2 * lc];
            pa[2] = *(const uint32_t*)&Ss[rlow  * PH + kt * 16 + 2 * lc + 8];
            pa[3] = *(const uint32_t*)&Ss[rhigh * PH + kt * 16 + 2 * lc + 8];
            #pragma unroll
            for (int nt = 0; nt < 2; nt++) {
                const int c = wn * 16 + nt * 8 + gid;   // output channel
                uint32_t b0 = *(const uint32_t*)&Vc[c * PH + kt * 16 + 2 * lc];
                uint32_t b1 = *(const uint32_t*)&Vc[c * PH + kt * 16 + 2 * lc + 8];
                mma_f16(acc[nt], pa, b0, b1);
            }
        }
    }

    __syncthreads();
    const float ilo = 1.f / srowl[rlow];
    const float ihi = 1.f / srowl[rhigh];

    float* ob = out + (size_t)b * CH * NTOK + m0;
    #pragma unroll
    for (int nt = 0; nt < 2; nt++) {
        const int c = wn * 16 + nt * 8 + 2 * lc;
        ob[(size_t)c * NTOK + rlow]        = acc[nt][0] * ilo;
        ob[(size_t)(c + 1) * NTOK + rlow]  = acc[nt][1] * ilo;
        ob[(size_t)c * NTOK + rhigh]       = acc[nt][2] * ihi;
        ob[(size_t)(c + 1) * NTOK + rhigh] = acc[nt][3] * ihi;
    }
}

// ---------------------------------------------------------------------------
extern "C" void kernel_launch(void* const* d_in, const int* in_sizes, int n_in,
                              void* d_out, int out_size)
{
    const float* x  = (const float*)d_in[0];
    const float* h  = (const float*)d_in[1];
    const float* Wq = (const float*)d_in[2];
    const float* bq = (const float*)d_in[3];
    const float* Wk = (const float*)d_in[4];
    const float* bk = (const float*)d_in[5];
    const float* Wv = (const float*)d_in[6];
    const float* bv = (const float*)d_in[7];
    float* out = (float*)d_out;

    cudaFuncSetAttribute(attn_kernel,
                         cudaFuncAttributeMaxDynamicSharedMemorySize, SMEM_BYTES);

    proj_kernel<<<dim3(NTOK / 128, BATCH, 3), 128>>>(x, h, Wq, bq, Wk, bk, Wv, bv);
    attn_kernel<<<dim3(NTOK / BM, BATCH), 512, SMEM_BYTES>>>(out);
}

// round 5
// speedup vs baseline: 6.4437x; 1.4632x over previous
#include <cuda_runtime.h>
#include <cuda_fp16.h>
#include <cstdint>

#define BATCH 2
#define CH    64
#define NTOK  4608
#define BM    64
#define BN    64
#define NT    72               // NTOK / BN
#define SCALE 0.125f
#define LOG2E 1.4426950408889634f
#define PH    72               // padded tile row length in halves (144 B)

// Scratch (fp16): Q,K token-major [B][N][C]; V channel-major [B][C][N]
__device__ __half g_Q[BATCH * NTOK * CH];
__device__ __half g_K[BATCH * NTOK * CH];
__device__ __half g_V[BATCH * CH * NTOK];

// ---------------------------------------------------------------------------
__device__ __forceinline__ void mma_f16(float* c, const uint32_t* a,
                                        uint32_t b0, uint32_t b1) {
    asm volatile(
        "mma.sync.aligned.m16n8k16.row.col.f32.f16.f16.f32 "
        "{%0,%1,%2,%3}, {%4,%5,%6,%7}, {%8,%9}, {%0,%1,%2,%3};"
        : "+f"(c[0]), "+f"(c[1]), "+f"(c[2]), "+f"(c[3])
        : "r"(a[0]), "r"(a[1]), "r"(a[2]), "r"(a[3]), "r"(b0), "r"(b1));
}
__device__ __forceinline__ void cp16(uint32_t dst, const void* src) {
    asm volatile("cp.async.ca.shared.global [%0], [%1], 16;"
                 :: "r"(dst), "l"(src));
}

// ---------------------------------------------------------------------------
// Projection -> fp16. z=0: Q from x (pre-scaled SCALE*LOG2E, [n][c]),
// z=1: K from h ([n][c]), z=2: V from h TRANSPOSED ([c][n]).
// ---------------------------------------------------------------------------
__global__ __launch_bounds__(128) void proj_kernel(
    const float* __restrict__ x, const float* __restrict__ h,
    const float* __restrict__ Wq, const float* __restrict__ bq,
    const float* __restrict__ Wk, const float* __restrict__ bk,
    const float* __restrict__ Wv, const float* __restrict__ bv)
{
    __shared__ float Ws[CH * CH];
    __shared__ float bs[CH];

    const int z = blockIdx.z;
    const float* inp  = (z == 0) ? x  : h;
    const float* W    = (z == 0) ? Wq : (z == 1) ? Wk : Wv;
    const float* bias = (z == 0) ? bq : (z == 1) ? bk : bv;

    const int tid = threadIdx.x;
    #pragma unroll
    for (int i = tid; i < CH * CH; i += 128) Ws[i] = W[i];
    if (tid < CH) bs[tid] = bias[tid];
    __syncthreads();

    const int b = blockIdx.y;
    const int n = blockIdx.x * 128 + tid;

    float acc[CH];
    #pragma unroll
    for (int o = 0; o < CH; o++) acc[o] = bs[o];

    const float* ic = inp + (size_t)b * CH * NTOK + n;
    #pragma unroll
    for (int c4 = 0; c4 < CH / 4; c4++) {
        const float x0 = ic[(size_t)(c4 * 4 + 0) * NTOK];
        const float x1 = ic[(size_t)(c4 * 4 + 1) * NTOK];
        const float x2 = ic[(size_t)(c4 * 4 + 2) * NTOK];
        const float x3 = ic[(size_t)(c4 * 4 + 3) * NTOK];
        #pragma unroll
        for (int o = 0; o < CH; o++) {
            const float4 w = *(const float4*)&Ws[o * CH + c4 * 4];
            acc[o] += w.x * x0 + w.y * x1 + w.z * x2 + w.w * x3;
        }
    }

    if (z == 2) {
        __half* vd = g_V + (size_t)b * CH * NTOK + n;
        #pragma unroll
        for (int o = 0; o < CH; o++)
            vd[(size_t)o * NTOK] = __float2half_rn(acc[o]);   // coalesced
    } else {
        if (z == 0) {
            const float qs = SCALE * LOG2E;
            #pragma unroll
            for (int o = 0; o < CH; o++) acc[o] *= qs;
        }
        __half* dst = ((z == 0) ? g_Q : g_K) + ((size_t)(b * NTOK + n)) * CH;
        #pragma unroll
        for (int o8 = 0; o8 < 8; o8++) {
            __half2 h0 = __floats2half2_rn(acc[o8 * 8 + 0], acc[o8 * 8 + 1]);
            __half2 h1 = __floats2half2_rn(acc[o8 * 8 + 2], acc[o8 * 8 + 3]);
            __half2 h2 = __floats2half2_rn(acc[o8 * 8 + 4], acc[o8 * 8 + 5]);
            __half2 h3 = __floats2half2_rn(acc[o8 * 8 + 6], acc[o8 * 8 + 7]);
            uint4 u;
            u.x = *(uint32_t*)&h0; u.y = *(uint32_t*)&h1;
            u.z = *(uint32_t*)&h2; u.w = *(uint32_t*)&h3;
            ((uint4*)dst)[o8] = u;            // per-thread contiguous 128B row
        }
    }
}

// ---------------------------------------------------------------------------
// FA2-style fp16 tensor-core attention. 128 threads = 4 warps.
// Warp w owns rows w*16..w*16+15 and ALL 64 kj -> softmax fully warp-local,
// P stays in registers (S C-frag layout == PV A-frag layout).
// Triple-buffered cp.async K/V stages; ONE barrier per tile.
// smem: Qs[64][PH] @0 (9216B); Ks[3][64][PH] @9216; Vs[3][64][PH] @36864.
// ---------------------------------------------------------------------------
#define QS_B 0
#define KS_B 9216
#define VS_B (KS_B + 3 * 9216)
#define SMEM_BYTES (VS_B + 3 * 9216)   // 64512

__global__ __launch_bounds__(128, 1) void attn_kernel(float* __restrict__ out)
{
    extern __shared__ char smc[];
    const uint32_t sb = (uint32_t)__cvta_generic_to_shared(smc);

    const int b    = blockIdx.y;
    const int m0   = blockIdx.x * BM;
    const int tid  = threadIdx.x;
    const int lane = tid & 31;
    const int w    = tid >> 5;
    const int gid  = lane >> 2;
    const int lc   = lane & 3;
    const int rlow  = w * 16 + gid;
    const int rhigh = rlow + 8;

    const int rr = tid >> 1;                 // staging row helper (Q: 64 rows)
    // staging: each stage = K 64x8 + V 64x8 chunks of 16B; 8 cp16/thread
    auto stage_kv = [&](int s, int tn) {
        #pragma unroll
        for (int i = 0; i < 4; i++) {
            const int j = tid + i * 128;     // 0..511
            const int r = j >> 3, c8 = j & 7;
            cp16(sb + KS_B + s * 9216 + r * 144 + c8 * 16,
                 g_K + ((size_t)(b * NTOK + tn * BN) + r) * CH + c8 * 8);
            cp16(sb + VS_B + s * 9216 + r * 144 + c8 * 16,
                 g_V + (size_t)b * CH * NTOK + (size_t)r * NTOK + tn * BN + c8 * 8);
        }
    };

    // ---- prologue: Q + stage0 (G0), stage1 (G1) ----
    {
        #pragma unroll
        for (int i = 0; i < 4; i++) {
            const int j = tid + i * 128;
            const int r = j >> 3, c8 = j & 7;
            cp16(sb + QS_B + r * 144 + c8 * 16,
                 g_Q + ((size_t)(b * NTOK + m0) + r) * CH + c8 * 8);
        }
        stage_kv(0, 0);
        asm volatile("cp.async.commit_group;");
        stage_kv(1, 1);
        asm volatile("cp.async.commit_group;");
        asm volatile("cp.async.wait_group 1;" ::: "memory");
        __syncthreads();
    }

    // ---- persistent Q A-fragments ----
    const __half* Qs = (const __half*)(smc + QS_B);
    uint32_t qa[4][4];
    #pragma unroll
    for (int kt = 0; kt < 4; kt++) {
        qa[kt][0] = *(const uint32_t*)&Qs[rlow  * PH + kt * 16 + 2 * lc];
        qa[kt][1] = *(const uint32_t*)&Qs[rhigh * PH + kt * 16 + 2 * lc];
        qa[kt][2] = *(const uint32_t*)&Qs[rlow  * PH + kt * 16 + 2 * lc + 8];
        qa[kt][3] = *(const uint32_t*)&Qs[rhigh * PH + kt * 16 + 2 * lc + 8];
    }

    float acc[8][4];
    #pragma unroll
    for (int nt = 0; nt < 8; nt++)
        #pragma unroll
        for (int i = 0; i < 4; i++) acc[nt][i] = 0.f;
    float mlo_run = -1e30f, mhi_run = -1e30f, llo = 0.f, lhi = 0.f;

    for (int t = 0; t < NT; t++) {
        if (t > 0) {
            asm volatile("cp.async.wait_group 1;" ::: "memory");
            __syncthreads();                 // the ONE barrier per tile
        }
        {   // prefetch stage t+2
            int tn = t + 2; if (tn >= NT) tn -= NT;
            stage_kv((t + 2) % 3, tn);
            asm volatile("cp.async.commit_group;");
        }

        // ---- scores: S[16][64] per warp (32 mma) ----
        const __half* Kc = (const __half*)(smc + KS_B + (t % 3) * 9216);
        float s[8][4];
        #pragma unroll
        for (int nt = 0; nt < 8; nt++)
            #pragma unroll
            for (int i = 0; i < 4; i++) s[nt][i] = 0.f;

        #pragma unroll
        for (int kt = 0; kt < 4; kt++) {
            #pragma unroll
            for (int nt = 0; nt < 8; nt++) {
                const int kj = nt * 8 + gid;
                uint32_t b0 = *(const uint32_t*)&Kc[kj * PH + kt * 16 + 2 * lc];
                uint32_t b1 = *(const uint32_t*)&Kc[kj * PH + kt * 16 + 2 * lc + 8];
                mma_f16(s[nt], qa[kt], b0, b1);
            }
        }

        // ---- warp-local softmax ----
        float tmlo = -1e30f, tmhi = -1e30f;
        #pragma unroll
        for (int nt = 0; nt < 8; nt++) {
            tmlo = fmaxf(tmlo, fmaxf(s[nt][0], s[nt][1]));
            tmhi = fmaxf(tmhi, fmaxf(s[nt][2], s[nt][3]));
        }
        tmlo = fmaxf(tmlo, __shfl_xor_sync(0xffffffffu, tmlo, 1));
        tmlo = fmaxf(tmlo, __shfl_xor_sync(0xffffffffu, tmlo, 2));
        tmhi = fmaxf(tmhi, __shfl_xor_sync(0xffffffffu, tmhi, 1));
        tmhi = fmaxf(tmhi, __shfl_xor_sync(0xffffffffu, tmhi, 2));
        const float mnlo = fmaxf(mlo_run, tmlo);
        const float mnhi = fmaxf(mhi_run, tmhi);
        const float alo  = exp2f(mlo_run - mnlo);
        const float ahi  = exp2f(mhi_run - mnhi);
        mlo_run = mnlo; mhi_run = mnhi;

        uint32_t pa[4][4];
        float slo = 0.f, shi = 0.f;
        #pragma unroll
        for (int nt = 0; nt < 8; nt++) {
            float p0 = exp2f(s[nt][0] - mnlo);
            float p1 = exp2f(s[nt][1] - mnlo);
            float p2 = exp2f(s[nt][2] - mnhi);
            float p3 = exp2f(s[nt][3] - mnhi);
            slo += p0 + p1;  shi += p2 + p3;
            __half2 lo2 = __floats2half2_rn(p0, p1);
            __half2 hi2 = __floats2half2_rn(p2, p3);
            pa[nt >> 1][(nt & 1) * 2]     = *(uint32_t*)&lo2;
            pa[nt >> 1][(nt & 1) * 2 + 1] = *(uint32_t*)&hi2;
        }
        slo += __shfl_xor_sync(0xffffffffu, slo, 1);
        slo += __shfl_xor_sync(0xffffffffu, slo, 2);
        shi += __shfl_xor_sync(0xffffffffu, shi, 1);
        shi += __shfl_xor_sync(0xffffffffu, shi, 2);
        llo = llo * alo + slo;
        lhi = lhi * ahi + shi;

        // ---- PV: O[16][64] += P[16][64] * V[64][64] (32 mma) ----
        #pragma unroll
        for (int nt = 0; nt < 8; nt++) {
            acc[nt][0] *= alo; acc[nt][1] *= alo;
            acc[nt][2] *= ahi; acc[nt][3] *= ahi;
        }
        const __half* Vc = (const __half*)(smc + VS_B + (t % 3) * 9216);
        #pragma unroll
        for (int kt = 0; kt < 4; kt++) {
            #pragma unroll
            for (int nt = 0; nt < 8; nt++) {
                const int c = nt * 8 + gid;
                uint32_t b0 = *(const uint32_t*)&Vc[c * PH + kt * 16 + 2 * lc];
                uint32_t b1 = *(const uint32_t*)&Vc[c * PH + kt * 16 + 2 * lc + 8];
                mma_f16(acc[nt], pa[kt], b0, b1);
            }
        }
    }

    // ---- epilogue: normalize + store (out is [b][c][n]) ----
    const float ilo = 1.f / llo;
    const float ihi = 1.f / lhi;
    float* ob = out + (size_t)b * CH * NTOK + m0;
    #pragma unroll
    for (int nt = 0; nt < 8; nt++) {
        const int c = nt * 8 + 2 * lc;
        ob[(size_t)c * NTOK + rlow]        = acc[nt][0] * ilo;
        ob[(size_t)(c + 1) * NTOK + rlow]  = acc[nt][1] * ilo;
        ob[(size_t)c * NTOK + rhigh]       = acc[nt][2] * ihi;
        ob[(size_t)(c + 1) * NTOK + rhigh] = acc[nt][3] * ihi;
    }
}

// ---------------------------------------------------------------------------
extern "C" void kernel_launch(void* const* d_in, const int* in_sizes, int n_in,
                              void* d_out, int out_size)
{
    const float* x  = (const float*)d_in[0];
    const float* h  = (const float*)d_in[1];
    const float* Wq = (const float*)d_in[2];
    const float* bq = (const float*)d_in[3];
    const float* Wk = (const float*)d_in[4];
    const float* bk = (const float*)d_in[5];
    const float* Wv = (const float*)d_in[6];
    const float* bv = (const float*)d_in[7];
    float* out = (float*)d_out;

    cudaFuncSetAttribute(attn_kernel,
                         cudaFuncAttributeMaxDynamicSharedMemorySize, SMEM_BYTES);

    proj_kernel<<<dim3(NTOK / 128, BATCH, 3), 128>>>(x, h, Wq, bq, Wk, bk, Wv, bv);
    attn_kernel<<<dim3(NTOK / BM, BATCH), 128, SMEM_BYTES>>>(out);
}